// round 11
// baseline (speedup 1.0000x reference)
#include <cuda_runtime.h>
#include <math.h>

#define EPSF 1e-8f
#define NB     64
#define NTOKP1 785
#define DIM    768
#define FH     28
#define NTOK   784
#define IMG    448
#define NCH    3
#define TOPK   8
#define PE     16
#define TGRP   7            // sim units per batch
#define TPG    112          // tokens per unit
#define NUNIT  (TGRP * NB)  // 448 sim units
#define SLICE  98           // tokens per warp in topk stage 1 (784/8)
#define ROWT   16           // output rows per crop tile
#define SROWS  18           // staged input rows (max span for 16 rows is 17)
#define NCTA   296          // 2 CTAs/SM x 148 SMs, all resident
#define NTHR   448
#define NTILE  (28 * NCH * NB)   // 5376 crop tiles

// scratch (no allocations allowed); device globals zero-initialized
__device__ float g_dist[NB][NTOK];
__device__ int   g_box[NB][4];
__device__ int   g_cnt[NB];     // sim-units-done per batch (self-resetting)
__device__ int   g_ready[NB];   // box published flag
__device__ int   g_fin;         // CTAs finished (self-resetting)

__device__ __forceinline__ int ld_acquire(const int* p) {
    int v;
    asm volatile("ld.acquire.gpu.global.b32 %0, [%1];" : "=r"(v) : "l"(p) : "memory");
    return v;
}

// ---------------------------------------------------------------------------
// ONE persistent kernel: sim units -> per-batch topk+box (release flag) ->
// crop tiles with per-batch acquire spin. 296 CTAs x 448 threads, all
// resident (launch_bounds(448,2)) => spins cannot deadlock.
// ---------------------------------------------------------------------------
__global__ __launch_bounds__(NTHR, 2)
void fused_kernel(const float* __restrict__ x,
                  const float* __restrict__ images,
                  float* __restrict__ out) {
    __shared__ float gs[DIM];
    __shared__ float red[14];
    __shared__ float sdist[NTOK];
    __shared__ float cval[64];
    __shared__ int   cidx[64];
    __shared__ int   s_last;
    __shared__ __align__(16) float srows[SROWS * IMG];   // 32.25 KB
    __shared__ int2  soff[ROWT];
    __shared__ float swy[ROWT];
    __shared__ int   sbox[4];

    const int tid  = threadIdx.x;
    const int lane = tid & 31;
    const int wid  = tid >> 5;

    // ======================= PHASE 1: similarity =======================
    for (int u = blockIdx.x; u < NUNIT; u += NCTA) {
        const int b   = u / TGRP;
        const int grp = u % TGRP;
        const float* __restrict__ xb = x + (size_t)b * NTOKP1 * DIM;

        // Load global token g into smem + sum of squares
        float ss = 0.f;
        for (int j = tid; j < DIM; j += NTHR) {
            float v = __ldg(xb + j);
            gs[j] = v;
            ss += v * v;
        }
        #pragma unroll
        for (int o = 16; o; o >>= 1) ss += __shfl_xor_sync(0xffffffffu, ss, o);
        if (lane == 0) red[wid] = ss;
        __syncthreads();
        if (tid == 0) {
            float s = 0.f;
            #pragma unroll
            for (int w = 0; w < 14; w++) s += red[w];
            red[0] = s;
        }
        __syncthreads();
        const float gn = fmaxf(sqrtf(red[0]), EPSF);

        // 14 warps x 4 pairs cover 112 tokens
        const int t_base = grp * TPG;
        #pragma unroll 1
        for (int p = 0; p < 4; p++) {
            const int t0 = t_base + 28 * p + wid;
            const int t1 = t0 + 14;
            const float* __restrict__ lr0 = xb + (size_t)(t0 + 1) * DIM;
            const float* __restrict__ lr1 = xb + (size_t)(t1 + 1) * DIM;
            float dot0 = 0.f, ls0 = 0.f, dot1 = 0.f, ls1 = 0.f;
            #pragma unroll
            for (int i = 0; i < 6; i++) {
                const int j = i * 128 + lane * 4;
                const float4 a0 = __ldcs((const float4*)(lr0 + j));
                const float4 a1 = __ldcs((const float4*)(lr1 + j));
                const float4 gv = *(const float4*)(gs + j);
                dot0 += a0.x * gv.x + a0.y * gv.y + a0.z * gv.z + a0.w * gv.w;
                ls0  += a0.x * a0.x + a0.y * a0.y + a0.z * a0.z + a0.w * a0.w;
                dot1 += a1.x * gv.x + a1.y * gv.y + a1.z * gv.z + a1.w * gv.w;
                ls1  += a1.x * a1.x + a1.y * a1.y + a1.z * a1.z + a1.w * a1.w;
            }
            #pragma unroll
            for (int o = 16; o; o >>= 1) {
                dot0 += __shfl_xor_sync(0xffffffffu, dot0, o);
                ls0  += __shfl_xor_sync(0xffffffffu, ls0, o);
                dot1 += __shfl_xor_sync(0xffffffffu, dot1, o);
                ls1  += __shfl_xor_sync(0xffffffffu, ls1, o);
            }
            if (lane == 0) {
                g_dist[b][t0] = dot0 / (gn * fmaxf(sqrtf(ls0), EPSF));
                g_dist[b][t1] = dot1 / (gn * fmaxf(sqrtf(ls1), EPSF));
            }
        }

        // ---- last-unit-per-batch: two-stage top-8 + box + release flag ----
        __threadfence();
        __syncthreads();
        if (tid == 0) {
            const int old = atomicAdd(&g_cnt[b], 1);
            s_last = (old == TGRP - 1);
            if (s_last) atomicExch(&g_cnt[b], 0);   // reset for next replay
        }
        __syncthreads();
        if (s_last) {
            __threadfence();
            for (int t = tid; t < NTOK; t += NTHR) sdist[t] = g_dist[b][t];
            __syncthreads();

            // Stage 1: warps 0..7, top-8 of disjoint 98-token slices
            if (wid < 8) {
                const int start = wid * SLICE;
                for (int k = 0; k < TOPK; k++) {
                    float bv = -3e38f;
                    int   bi = 0x7fffffff;
                    for (int t = start + lane; t < start + SLICE; t += 32) {
                        const float v = sdist[t];
                        if (v > bv || (v == bv && t < bi)) { bv = v; bi = t; }
                    }
                    #pragma unroll
                    for (int o = 16; o; o >>= 1) {
                        const float ov = __shfl_xor_sync(0xffffffffu, bv, o);
                        const int   oi = __shfl_xor_sync(0xffffffffu, bi, o);
                        if (ov > bv || (ov == bv && oi < bi)) { bv = ov; bi = oi; }
                    }
                    if (lane == 0) {
                        sdist[bi] = -3e38f;
                        cval[wid * TOPK + k] = bv;
                        cidx[wid * TOPK + k] = bi;
                    }
                    __syncwarp();
                }
            }
            __syncthreads();

            // Stage 2: warp 0 merges 64 candidates (2 per lane)
            if (wid == 0) {
                float v0 = cval[lane], v1 = cval[lane + 32];
                int   i0 = cidx[lane], i1 = cidx[lane + 32];
                int minR = FH, maxR = -1, minC = FH, maxC = -1;
                for (int k = 0; k < TOPK; k++) {
                    float bv; int bi;
                    if (v0 > v1 || (v0 == v1 && i0 < i1)) { bv = v0; bi = i0; }
                    else                                  { bv = v1; bi = i1; }
                    #pragma unroll
                    for (int o = 16; o; o >>= 1) {
                        const float ov = __shfl_xor_sync(0xffffffffu, bv, o);
                        const int   oi = __shfl_xor_sync(0xffffffffu, bi, o);
                        if (ov > bv || (ov == bv && oi < bi)) { bv = ov; bi = oi; }
                    }
                    if (i0 == bi) { v0 = -3e38f; i0 = 0x7fffffff; }
                    if (i1 == bi) { v1 = -3e38f; i1 = 0x7fffffff; }
                    const int r = bi / FH, c = bi % FH;
                    minR = min(minR, r); maxR = max(maxR, r);
                    minC = min(minC, c); maxC = max(maxC, c);
                }
                if (lane == 0) {
                    const int x_i = minR * PE, x_f = maxR * PE;
                    const int y_i = minC * PE, y_f = maxC * PE;
                    g_box[b][0] = max(x_i, 0);
                    g_box[b][1] = min(max(x_f, x_i + PE), IMG);
                    g_box[b][2] = max(y_i, 0);
                    g_box[b][3] = min(max(y_f, y_i + PE), IMG);
                    __threadfence();                 // publish box
                    atomicExch(&g_ready[b], 1);      // release flag
                }
            }
            __syncthreads();
        }
    }

    // ======================= PHASE 2: crop tiles =======================
    int last_b = -1;
    for (int t = blockIdx.x; t < NTILE; t += NCTA) {
        const int b   = t / (28 * NCH);
        const int rem = t % (28 * NCH);
        const int c   = rem / 28;
        const int rt  = rem % 28;

        if (b != last_b) {
            if (tid == 0) {
                while (ld_acquire(&g_ready[b]) == 0) __nanosleep(64);
                sbox[0] = g_box[b][0]; sbox[1] = g_box[b][1];
                sbox[2] = g_box[b][2]; sbox[3] = g_box[b][3];
            }
            last_b = b;
        }
        __syncthreads();     // box visible + srows/soff safe to overwrite

        const int x0 = sbox[0], x1 = sbox[1];
        const int y0 = sbox[2], y1 = sbox[3];
        const int ox = tid;

        const float scale = (float)(1.0 / 447.0);
        const float hm1 = __fadd_rn((float)(x1 - x0), -1.0f);
        const float wm1 = __fadd_rn((float)(y1 - y0), -1.0f);

        // Vertical input-row range for this tile (sy monotone in oy).
        const int oy0 = rt * ROWT;
        const float syA = __fadd_rn((float)x0, __fmul_rn(__fmul_rn((float)oy0, hm1), scale));
        const float syB = __fadd_rn((float)x0, __fmul_rn(__fmul_rn((float)(oy0 + ROWT - 1), hm1), scale));
        const int ystart = (int)floorf(syA);
        const int yloB   = (int)floorf(syB);
        const int yend   = max(yloB, min(yloB + 1, x1 - 1));
        const int nrows  = yend - ystart + 1;        // <= 18
        const int wspan  = y1 - y0;                  // multiple of 16

        // Stage rows with 16B cp.async (y0 multiple of 16 -> aligned span).
        const float* __restrict__ img = images + (size_t)(b * NCH + c) * IMG * IMG;
        const int nthr4 = wspan >> 2;
        if (ox < nthr4) {
            unsigned das = (unsigned)__cvta_generic_to_shared(srows) + ox * 16;
            const float* __restrict__ src = img + (size_t)ystart * IMG + y0 + ox * 4;
            #pragma unroll 3
            for (int r = 0; r < nrows; r++) {
                asm volatile("cp.async.cg.shared.global [%0], [%1], 16;"
                             :: "r"(das + r * IMG * 4), "l"(src + (size_t)r * IMG));
            }
        }
        asm volatile("cp.async.commit_group;");

        // Vertical coords: thread-invariant -> 16 threads fill all rows.
        if (ox < ROWT) {
            const int oy = oy0 + ox;
            const float sy  = __fadd_rn((float)x0, __fmul_rn(__fmul_rn((float)oy, hm1), scale));
            const int   ylo = (int)floorf(sy);
            const int   yhi = min(ylo + 1, x1 - 1);
            soff[ox] = make_int2((ylo - ystart) * IMG, (yhi - ystart) * IMG);
            swy[ox]  = __fadd_rn(sy, -(float)ylo);
        }

        // Horizontal coords (row-invariant) — overlap staging flight.
        const float sx = __fadd_rn((float)y0, __fmul_rn(__fmul_rn((float)ox, wm1), scale));
        const int   xlo = (int)floorf(sx);
        const int   xhi = min(xlo + 1, y1 - 1);
        const float wx  = __fadd_rn(sx, -(float)xlo);
        const int   clo = xlo - y0;
        const int   chi = xhi - y0;

        asm volatile("cp.async.wait_group 0;");
        __syncthreads();

        float* __restrict__ op = out + ((size_t)(b * NCH + c) * IMG + oy0) * IMG + ox;

        #pragma unroll 4
        for (int r = 0; r < ROWT; r++) {
            const int2  off = soff[r];
            const float wy  = swy[r];
            const float* __restrict__ s0 = srows + off.x;
            const float* __restrict__ s1 = srows + off.y;
            const float v00 = s0[clo];
            const float v01 = s0[chi];
            const float v10 = s1[clo];
            const float v11 = s1[chi];
            const float h0 = v00 + wx * (v01 - v00);
            const float h1 = v10 + wx * (v11 - v10);
            const float res = h0 + wy * (h1 - h0);
            __stcs(op + (size_t)r * IMG, res);
        }
        __syncthreads();   // srows reused next iteration
    }

    // ---- self-reset for next graph replay: last CTA clears flags ----
    if (tid == 0) {
        __threadfence();
        const int old = atomicAdd(&g_fin, 1);
        if (old == NCTA - 1) {
            for (int i = 0; i < NB; i++) g_ready[i] = 0;
            __threadfence();
            atomicExch(&g_fin, 0);
        }
    }
}

// ---------------------------------------------------------------------------
extern "C" void kernel_launch(void* const* d_in, const int* in_sizes, int n_in,
                              void* d_out, int out_size) {
    const float* x      = (const float*)d_in[0];   // (64, 785, 768) fp32
    const float* images = (const float*)d_in[1];   // (64, 3, 448, 448) fp32
    float* out = (float*)d_out;                    // (64, 3, 448, 448) fp32

    fused_kernel<<<NCTA, NTHR>>>(x, images, out);
}

// round 14
// speedup vs baseline: 1.1210x; 1.1210x over previous
#include <cuda_runtime.h>
#include <math.h>

#define EPSF 1e-8f
#define NB     64
#define NTOKP1 785
#define DIM    768
#define FH     28
#define NTOK   784
#define IMG    448
#define NCH    3
#define TOPK   8
#define PE     16
#define NBH    32           // batches per tranche
#define UNITB  14           // sim units per batch
#define TPG    56           // tokens per unit (784/14)
#define SLICE  98           // tokens per warp in topk stage 1 (784/8)
#define ROWT   16           // output rows per crop tile
#define SROWS  18           // staged input rows
#define NTILE  (28 * NCH * NB)

// scratch (no allocations allowed); device globals zero-initialized
__device__ float g_dist[NB][NTOK];
__device__ int   g_box[NB][4];
__device__ int   g_cnt[NB];     // sim units done per batch (self-resetting)
__device__ int   g_ready[NB];   // box published flag
__device__ int   g_fin;         // crop CTAs finished (self-resetting)

__device__ __forceinline__ int ld_acquire(const int* p) {
    int v;
    asm volatile("ld.acquire.gpu.global.b32 %0, [%1];" : "=r"(v) : "l"(p) : "memory");
    return v;
}

// ---------------------------------------------------------------------------
// Kernel A: sim + topk + box, two batch tranches. grid (14 units, 32 b_local),
// 256 thr -> 448 CTAs = one fully-resident wave. Fires the PDL trigger at
// entry so the crop kernel launches immediately and overlaps tranche 2.
// ---------------------------------------------------------------------------
__global__ __launch_bounds__(256)
void sim_box_kernel(const float* __restrict__ x) {
    // allow dependent (crop) grid to launch now; ordering is via g_ready flags
    asm volatile("griddepcontrol.launch_dependents;" ::: "memory");

    __shared__ float gs[DIM];
    __shared__ float red[8];
    __shared__ float sdist[NTOK];
    __shared__ float cval[64];
    __shared__ int   cidx[64];
    __shared__ int   s_last;

    const int unit = blockIdx.x;
    const int tid  = threadIdx.x;
    const int lane = tid & 31;
    const int wid  = tid >> 5;

    #pragma unroll 1
    for (int tr = 0; tr < 2; tr++) {
        const int b = blockIdx.y + NBH * tr;
        const float* __restrict__ xb = x + (size_t)b * NTOKP1 * DIM;

        // Load global token g into smem + sum of squares
        float ss = 0.f;
        for (int j = tid; j < DIM; j += 256) {
            float v = __ldg(xb + j);
            gs[j] = v;
            ss += v * v;
        }
        #pragma unroll
        for (int o = 16; o; o >>= 1) ss += __shfl_xor_sync(0xffffffffu, ss, o);
        if (lane == 0) red[wid] = ss;
        __syncthreads();
        if (tid == 0) {
            float s = 0.f;
            #pragma unroll
            for (int w = 0; w < 8; w++) s += red[w];
            red[0] = s;
        }
        __syncthreads();
        const float gn = fmaxf(sqrtf(red[0]), EPSF);

        // 8 warps cover 56 tokens: 3 pair-iters + 1 single
        const int t_base = unit * TPG;
        #pragma unroll 1
        for (int p = 0; p < 3; p++) {
            const int t0 = t_base + wid + 16 * p;
            const int t1 = t0 + 8;
            const float* __restrict__ lr0 = xb + (size_t)(t0 + 1) * DIM;
            const float* __restrict__ lr1 = xb + (size_t)(t1 + 1) * DIM;
            float dot0 = 0.f, ls0 = 0.f, dot1 = 0.f, ls1 = 0.f;
            #pragma unroll
            for (int i = 0; i < 6; i++) {
                const int j = i * 128 + lane * 4;
                const float4 a0 = __ldcs((const float4*)(lr0 + j));
                const float4 a1 = __ldcs((const float4*)(lr1 + j));
                const float4 gv = *(const float4*)(gs + j);
                dot0 += a0.x * gv.x + a0.y * gv.y + a0.z * gv.z + a0.w * gv.w;
                ls0  += a0.x * a0.x + a0.y * a0.y + a0.z * a0.z + a0.w * a0.w;
                dot1 += a1.x * gv.x + a1.y * gv.y + a1.z * gv.z + a1.w * gv.w;
                ls1  += a1.x * a1.x + a1.y * a1.y + a1.z * a1.z + a1.w * a1.w;
            }
            #pragma unroll
            for (int o = 16; o; o >>= 1) {
                dot0 += __shfl_xor_sync(0xffffffffu, dot0, o);
                ls0  += __shfl_xor_sync(0xffffffffu, ls0, o);
                dot1 += __shfl_xor_sync(0xffffffffu, dot1, o);
                ls1  += __shfl_xor_sync(0xffffffffu, ls1, o);
            }
            if (lane == 0) {
                g_dist[b][t0] = dot0 / (gn * fmaxf(sqrtf(ls0), EPSF));
                g_dist[b][t1] = dot1 / (gn * fmaxf(sqrtf(ls1), EPSF));
            }
        }
        {   // last 8 tokens (one per warp)
            const int t0 = t_base + wid + 48;
            const float* __restrict__ lr0 = xb + (size_t)(t0 + 1) * DIM;
            float dot0 = 0.f, ls0 = 0.f;
            #pragma unroll
            for (int i = 0; i < 6; i++) {
                const int j = i * 128 + lane * 4;
                const float4 a0 = __ldcs((const float4*)(lr0 + j));
                const float4 gv = *(const float4*)(gs + j);
                dot0 += a0.x * gv.x + a0.y * gv.y + a0.z * gv.z + a0.w * gv.w;
                ls0  += a0.x * a0.x + a0.y * a0.y + a0.z * a0.z + a0.w * a0.w;
            }
            #pragma unroll
            for (int o = 16; o; o >>= 1) {
                dot0 += __shfl_xor_sync(0xffffffffu, dot0, o);
                ls0  += __shfl_xor_sync(0xffffffffu, ls0, o);
            }
            if (lane == 0)
                g_dist[b][t0] = dot0 / (gn * fmaxf(sqrtf(ls0), EPSF));
        }

        // ---- last-unit-per-batch: two-stage top-8 + box + release flag ----
        __threadfence();
        __syncthreads();
        if (tid == 0) {
            const int old = atomicAdd(&g_cnt[b], 1);
            s_last = (old == UNITB - 1);
            if (s_last) atomicExch(&g_cnt[b], 0);   // reset for next replay
        }
        __syncthreads();
        if (s_last) {
            __threadfence();
            for (int t = tid; t < NTOK; t += 256) sdist[t] = g_dist[b][t];
            __syncthreads();

            // Stage 1: 8 warps, top-8 of disjoint 98-token slices
            {
                const int start = wid * SLICE;
                for (int k = 0; k < TOPK; k++) {
                    float bv = -3e38f;
                    int   bi = 0x7fffffff;
                    for (int t = start + lane; t < start + SLICE; t += 32) {
                        const float v = sdist[t];
                        if (v > bv || (v == bv && t < bi)) { bv = v; bi = t; }
                    }
                    #pragma unroll
                    for (int o = 16; o; o >>= 1) {
                        const float ov = __shfl_xor_sync(0xffffffffu, bv, o);
                        const int   oi = __shfl_xor_sync(0xffffffffu, bi, o);
                        if (ov > bv || (ov == bv && oi < bi)) { bv = ov; bi = oi; }
                    }
                    if (lane == 0) {
                        sdist[bi] = -3e38f;
                        cval[wid * TOPK + k] = bv;
                        cidx[wid * TOPK + k] = bi;
                    }
                    __syncwarp();
                }
            }
            __syncthreads();

            // Stage 2: warp 0 merges 64 candidates (2 per lane)
            if (wid == 0) {
                float v0 = cval[lane], v1 = cval[lane + 32];
                int   i0 = cidx[lane], i1 = cidx[lane + 32];
                int minR = FH, maxR = -1, minC = FH, maxC = -1;
                for (int k = 0; k < TOPK; k++) {
                    float bv; int bi;
                    if (v0 > v1 || (v0 == v1 && i0 < i1)) { bv = v0; bi = i0; }
                    else                                  { bv = v1; bi = i1; }
                    #pragma unroll
                    for (int o = 16; o; o >>= 1) {
                        const float ov = __shfl_xor_sync(0xffffffffu, bv, o);
                        const int   oi = __shfl_xor_sync(0xffffffffu, bi, o);
                        if (ov > bv || (ov == bv && oi < bi)) { bv = ov; bi = oi; }
                    }
                    if (i0 == bi) { v0 = -3e38f; i0 = 0x7fffffff; }
                    if (i1 == bi) { v1 = -3e38f; i1 = 0x7fffffff; }
                    const int r = bi / FH, c = bi % FH;
                    minR = min(minR, r); maxR = max(maxR, r);
                    minC = min(minC, c); maxC = max(maxC, c);
                }
                if (lane == 0) {
                    const int x_i = minR * PE, x_f = maxR * PE;
                    const int y_i = minC * PE, y_f = maxC * PE;
                    g_box[b][0] = max(x_i, 0);
                    g_box[b][1] = min(max(x_f, x_i + PE), IMG);
                    g_box[b][2] = max(y_i, 0);
                    g_box[b][3] = min(max(y_f, y_i + PE), IMG);
                    __threadfence();                 // publish box
                    atomicExch(&g_ready[b], 1);      // release flag
                }
            }
            __syncthreads();
        }
    }
}

// ---------------------------------------------------------------------------
// Kernel B: bilinear crop-resize (align_corners), 16 rows per CTA, launched
// via PDL (PSS); spins on the per-batch ready flag before staging.
// grid = (28 row-tiles, 3 channels, 64 batches), block = 448 threads.
// ---------------------------------------------------------------------------
__global__ __launch_bounds__(IMG)
void crop_resize_kernel(const float* __restrict__ images, float* __restrict__ out) {
    __shared__ __align__(16) float srows[SROWS * IMG];   // 32.25 KB
    __shared__ int2  soff[ROWT];
    __shared__ float swy[ROWT];
    __shared__ int   sbox[4];

    const int rt = blockIdx.x;
    const int c  = blockIdx.y;
    const int b  = blockIdx.z;
    const int ox = threadIdx.x;

    if (ox == 0) {
        while (ld_acquire(&g_ready[b]) == 0) __nanosleep(256);
        sbox[0] = g_box[b][0]; sbox[1] = g_box[b][1];
        sbox[2] = g_box[b][2]; sbox[3] = g_box[b][3];
    }
    __syncthreads();

    const int x0 = sbox[0], x1 = sbox[1];
    const int y0 = sbox[2], y1 = sbox[3];

    const float scale = (float)(1.0 / 447.0);
    const float hm1 = __fadd_rn((float)(x1 - x0), -1.0f);
    const float wm1 = __fadd_rn((float)(y1 - y0), -1.0f);

    // Vertical input-row range for this tile (sy monotone in oy).
    const int oy0 = rt * ROWT;
    const float syA = __fadd_rn((float)x0, __fmul_rn(__fmul_rn((float)oy0, hm1), scale));
    const float syB = __fadd_rn((float)x0, __fmul_rn(__fmul_rn((float)(oy0 + ROWT - 1), hm1), scale));
    const int ystart = (int)floorf(syA);
    const int yloB   = (int)floorf(syB);
    const int yend   = max(yloB, min(yloB + 1, x1 - 1));
    const int nrows  = yend - ystart + 1;        // <= 18
    const int wspan  = y1 - y0;                  // multiple of 16

    // Stage rows with 16B cp.async (y0 multiple of 16 -> aligned span).
    const float* __restrict__ img = images + (size_t)(b * NCH + c) * IMG * IMG;
    const int nthr4 = wspan >> 2;
    if (ox < nthr4) {
        unsigned das = (unsigned)__cvta_generic_to_shared(srows) + ox * 16;
        const float* __restrict__ src = img + (size_t)ystart * IMG + y0 + ox * 4;
        #pragma unroll 3
        for (int r = 0; r < nrows; r++) {
            asm volatile("cp.async.cg.shared.global [%0], [%1], 16;"
                         :: "r"(das + r * IMG * 4), "l"(src + (size_t)r * IMG));
        }
    }
    asm volatile("cp.async.commit_group;");

    // Vertical coords: thread-invariant -> 16 threads fill all rows.
    if (ox < ROWT) {
        const int oy = oy0 + ox;
        const float sy  = __fadd_rn((float)x0, __fmul_rn(__fmul_rn((float)oy, hm1), scale));
        const int   ylo = (int)floorf(sy);
        const int   yhi = min(ylo + 1, x1 - 1);
        soff[ox] = make_int2((ylo - ystart) * IMG, (yhi - ystart) * IMG);
        swy[ox]  = __fadd_rn(sy, -(float)ylo);
    }

    // Horizontal coords (row-invariant) — overlap staging flight.
    const float sx = __fadd_rn((float)y0, __fmul_rn(__fmul_rn((float)ox, wm1), scale));
    const int   xlo = (int)floorf(sx);
    const int   xhi = min(xlo + 1, y1 - 1);
    const float wx  = __fadd_rn(sx, -(float)xlo);
    const int   clo = xlo - y0;
    const int   chi = xhi - y0;

    asm volatile("cp.async.wait_group 0;");
    __syncthreads();

    float* __restrict__ op = out + ((size_t)(b * NCH + c) * IMG + oy0) * IMG + ox;

    #pragma unroll 4
    for (int r = 0; r < ROWT; r++) {
        const int2  off = soff[r];
        const float wy  = swy[r];
        const float* __restrict__ s0 = srows + off.x;
        const float* __restrict__ s1 = srows + off.y;
        const float v00 = s0[clo];
        const float v01 = s0[chi];
        const float v10 = s1[clo];
        const float v11 = s1[chi];
        const float h0 = v00 + wx * (v01 - v00);
        const float h1 = v10 + wx * (v11 - v10);
        const float res = h0 + wy * (h1 - h0);
        __stcs(op + (size_t)r * IMG, res);
    }

    // ---- self-reset flags for next graph replay (last crop CTA) ----
    if (ox == 0) {
        __threadfence();
        const int old = atomicAdd(&g_fin, 1);
        if (old == NTILE - 1) {
            for (int i = 0; i < NB; i++) g_ready[i] = 0;
            __threadfence();
            atomicExch(&g_fin, 0);
        }
    }
}

// ---------------------------------------------------------------------------
extern "C" void kernel_launch(void* const* d_in, const int* in_sizes, int n_in,
                              void* d_out, int out_size) {
    const float* x      = (const float*)d_in[0];   // (64, 785, 768) fp32
    const float* images = (const float*)d_in[1];   // (64, 3, 448, 448) fp32
    float* out = (float*)d_out;                    // (64, 3, 448, 448) fp32

    dim3 gridA(UNITB, NBH);
    sim_box_kernel<<<gridA, 256>>>(x);

    // crop: programmatic dependent launch — starts as soon as sim triggers
    cudaLaunchConfig_t cfg = {};
    cfg.gridDim  = dim3(IMG / ROWT, NCH, NB);
    cfg.blockDim = dim3(IMG, 1, 1);
    cfg.dynamicSmemBytes = 0;
    cfg.stream = 0;
    cudaLaunchAttribute attr[1];
    attr[0].id = cudaLaunchAttributeProgrammaticStreamSerialization;
    attr[0].val.programmaticStreamSerializationAllowed = 1;
    cfg.attrs = attr;
    cfg.numAttrs = 1;
    cudaLaunchKernelEx(&cfg, crop_resize_kernel, images, out);
}